// round 15
// baseline (speedup 1.0000x reference)
#include <cuda_runtime.h>
#include <cuda_fp16.h>
#include <cstdint>

// ---------------------------------------------------------------------------
// FPN head via legacy tensor cores (mma.sync m16n8k16 f16, fp32 accum).
// R15: warp tile 64o x 64n (block 128o x 64n, R=2 x TW=32) -> 1.0 L1-wf/MMA
// (was 1.5) and -40% staging per MMA. 5 blocks/SM (64 thr, ~180 regs,
// 35.8KB smem) keeps 5 barrier domains. Single-phase staging, one barrier,
// sync-free 72-step MMA stream. Fused single launch for all levels + p5.
// Output: [64, 240] fp32  (c1:128 | c2:64 | c3:32 | c4:16)
// ---------------------------------------------------------------------------

typedef unsigned int u32;

// A fragment image: [l][gi(36)][rg(8)][ks(2)][lane(32)] x uint4
__device__ uint4 g_wA[3 * 36 * 8 * 2 * 32];

// per-block smem: sCol(64f)/p5 scratch @0, B @1024: 136 pos x 256 B
#define SMEM_BYTES 35840   // 1024 + 136*256

// ---- PTX helpers ----------------------------------------------------------
__device__ __forceinline__ u32 smem_u32(const void* p) {
    u32 a;
    asm("{ .reg .u64 t; cvta.to.shared.u64 t, %1; cvt.u32.u64 %0, t; }"
        : "=r"(a) : "l"(p));
    return a;
}
__device__ __forceinline__ void ldm_x4(u32* r, u32 addr) {
    asm volatile("ldmatrix.sync.aligned.m8n8.x4.shared.b16 {%0,%1,%2,%3}, [%4];"
                 : "=r"(r[0]), "=r"(r[1]), "=r"(r[2]), "=r"(r[3]) : "r"(addr));
}
__device__ __forceinline__ void mma16816(float* d, const uint4 a, u32 b0, u32 b1) {
    asm volatile(
        "mma.sync.aligned.m16n8k16.row.col.f32.f16.f16.f32 "
        "{%0,%1,%2,%3}, {%4,%5,%6,%7}, {%8,%9}, {%0,%1,%2,%3};"
        : "+f"(d[0]), "+f"(d[1]), "+f"(d[2]), "+f"(d[3])
        : "r"(a.x), "r"(a.y), "r"(a.z), "r"(a.w), "r"(b0), "r"(b1));
}

// ---- weight prep + out init fused -----------------------------------------
__global__ void prep_kernel(const float* __restrict__ w1,
                            const float* __restrict__ w2,
                            const float* __restrict__ w3,
                            const float* __restrict__ bpl1,
                            const float* __restrict__ bpl2,
                            const float* __restrict__ bpl3,
                            float* __restrict__ out) {
    int i = blockIdx.x * 256 + threadIdx.x;
    if (i < 3 * 36 * 2048) {
        int q    = i & 3;
        int lane = (i >> 2) & 31;
        int ks   = (i >> 7) & 1;
        int rg   = (i >> 8) & 7;
        int gi   = (i >> 11) % 36;
        int l    = i / (36 << 11);
        const float* src = (l == 0) ? w1 : (l == 1) ? w2 : w3;
        int o = rg * 16 + (lane >> 2) + (q & 1) * 8;
        int k = ks * 16 + (lane & 3) * 2 + (q >> 1) * 8;
        int c = (gi / 9) * 32 + k;
        int tap = gi % 9;
        __half2 hv = __floats2half2_rn(src[o * 1152 + c * 9 + tap],
                                       src[o * 1152 + (c + 1) * 9 + tap]);
        ((u32*)g_wA)[i] = *(u32*)&hv;
    } else {
        int j2 = i - 3 * 36 * 2048;
        if (j2 >= 64 * 224) return;
        int j = j2 % 224;
        out[(j2 / 224) * 240 + j] =
            (j < 128) ? bpl1[0] : (j < 192) ? bpl2[0] : bpl3[0];
    }
}

// ---- conv tile worker ------------------------------------------------------
// 64 threads = 2 warps (warpm 0/1, each 64o x 64n). Block tile 128o x 64n =
// R(2) rows x TW(32) cols stripe.
// SMEM: sCol(64f)@0, B @1024: [(R+2)*(TW+2)=136 pos][128 f16 = 256 B],
//   16B-block swizzle: block kb at position p stored at slot kb ^ (p & 7).
template <int H, int W, int BASE>
__device__ void conv_tile_impl(
    int tbid, const float* __restrict__ x, const uint4* __restrict__ wA,
    const float* __restrict__ bs, const float* __restrict__ wt,
    const float* __restrict__ bt, const float* __restrict__ wpl,
    float* __restrict__ out, char* smem) {
    constexpr int TW = 32;
    constexpr int R = 2;
    constexpr int NW = TW + 2;
    constexpr int B_OFF = 1024;
    constexpr int CT = W / TW;
    constexpr int TW4 = TW / 4;

    float* sCol = (float*)smem;
    const u32 smu = smem_u32(smem);
    const u32 bbase = smu + B_OFF;

    const int tid = threadIdx.x;
    const int warpm = tid >> 5;        // 0..1
    const int lane = tid & 31;

    const int TPB = (H / R) * CT;
    const int b = tbid / TPB;
    const int rem = tbid - b * TPB;
    const int h0 = (rem / CT) * R;
    const int w0 = (rem - (rem / CT) * CT) * TW;
    const float* xb = x + (size_t)b * 128 * H * W;

    sCol[tid] = 0.f;   // 64 floats

    // hoisted B-tile geometry (4 ldmatrix groups, each 16 n)
    int p0[4];
#pragma unroll
    for (int j = 0; j < 4; j++) {
        int ng = j * 16 + (lane >> 4) * 8;   // 0,8,...,56
        int trow = ng >> 5;                  // row within R (TW=32)
        int tcol = ng & (TW - 1);
        p0[j] = trow * NW + tcol + (lane & 7);
    }
    const int kbh = (lane >> 3) & 1;

    float d[4][8][4];
#pragma unroll
    for (int mi = 0; mi < 4; mi++)
#pragma unroll
        for (int nj = 0; nj < 8; nj++)
#pragma unroll
            for (int q = 0; q < 4; q++) d[mi][nj][q] = 0.f;

    // ---- single-phase staging: all 128 channels ---------------------------
    {
#pragma unroll 1
        for (int cpr = 0; cpr < 4; cpr++) {
            const int cp = (tid >> 2) + cpr * 16;     // half2 pair 0..63
            const int kb = cp >> 2;                   // 16B block 0..15
            const int cw = cp & 3;                    // u32 within block
            const float* xc0 = xb + (size_t)(2 * cp) * H * W;
            // halo columns (w = -1 and w = TW)
            for (int it = tid & 3; it < (R + 2) * 2; it += 4) {
                int r = it >> 1;
                int w = (it & 1) * (NW - 1);
                int gh = h0 + r - 1;
                int gw = w0 + w - 1;
                float v0 = 0.f, v1 = 0.f;
                if (gh >= 0 && gh < H && (unsigned)gw < (unsigned)W) {
                    const float* bp = xc0 + gh * W + gw;
                    v0 = bp[0];
                    v1 = bp[H * W];
                }
                int p = r * NW + w;
                __half2 hv = __floats2half2_rn(v0, v1);
                int word = p * 64 + ((kb ^ (p & 7)) << 2) + cw;
                *(__half2*)(smem + B_OFF + word * 4) = hv;
            }
            // interior: float4 loads (4 positions per LDG)
            for (int it = tid & 3; it < (R + 2) * TW4; it += 4) {
                int r = it / TW4;
                int w4 = (it - r * TW4) * 4;
                int gh = h0 + r - 1;
                float4 v0 = {0.f, 0.f, 0.f, 0.f}, v1 = v0;
                if (gh >= 0 && gh < H) {
                    const float* bp = xc0 + gh * W + (w0 + w4);
                    v0 = *(const float4*)bp;
                    v1 = *(const float4*)(bp + H * W);
                }
                const float* f0 = (const float*)&v0;
                const float* f1 = (const float*)&v1;
#pragma unroll
                for (int dw = 0; dw < 4; dw++) {
                    int p = r * NW + w4 + dw + 1;
                    __half2 hv = __floats2half2_rn(f0[dw], f1[dw]);
                    int word = p * 64 + ((kb ^ (p & 7)) << 2) + cw;
                    *(__half2*)(smem + B_OFF + word * 4) = hv;
                }
            }
        }
    }
    __syncthreads();   // the ONLY pre-MMA barrier

    // ---- sync-free MMA stream: 4 cc (rolled) x 9 taps x 2 ks --------------
#pragma unroll 1
    for (int cc = 0; cc < 4; cc++) {
#pragma unroll
        for (int tap = 0; tap < 9; tap++) {
            const int gi = cc * 9 + tap;
            const int dy = tap / 3;
            const int dx = tap - dy * 3;
            const int pofs = dy * NW + dx;
#pragma unroll
            for (int ks = 0; ks < 2; ks++) {
                uint4 a[4];
#pragma unroll
                for (int mi = 0; mi < 4; mi++) {
                    int rg = warpm * 4 + mi;
                    a[mi] = wA[((gi * 8 + rg) * 2 + ks) * 32 + lane];
                }
                const int kb = cc * 4 + ks * 2 + kbh;   // 0..15
#pragma unroll
                for (int j = 0; j < 4; j++) {
                    int p = p0[j] + pofs;
                    u32 bf[4];
                    ldm_x4(bf, bbase + p * 256 + ((kb ^ (p & 7)) << 4));
#pragma unroll
                    for (int mi = 0; mi < 4; mi++) {
                        mma16816(d[mi][2 * j], a[mi], bf[0], bf[1]);
                        mma16816(d[mi][2 * j + 1], a[mi], bf[2], bf[3]);
                    }
                }
            }
        }
    }

    // ---- epilogue: bias + ReLU + dot(w_t), reduce, pool -------------------
    const int g = lane >> 2;
    const int tid4 = lane & 3;
    float bsv[4][2], wtv[4][2];
#pragma unroll
    for (int mi = 0; mi < 4; mi++)
#pragma unroll
        for (int hh = 0; hh < 2; hh++) {
            int o = warpm * 64 + mi * 16 + hh * 8 + g;
            bsv[mi][hh] = bs[o];
            wtv[mi][hh] = wt[o];
        }
    __syncthreads();
#pragma unroll
    for (int nj = 0; nj < 8; nj++) {
        float v0 = 0.f, v1 = 0.f;
#pragma unroll
        for (int mi = 0; mi < 4; mi++) {
            v0 += fmaxf(d[mi][nj][0] + bsv[mi][0], 0.f) * wtv[mi][0]
                + fmaxf(d[mi][nj][2] + bsv[mi][1], 0.f) * wtv[mi][1];
            v1 += fmaxf(d[mi][nj][1] + bsv[mi][0], 0.f) * wtv[mi][0]
                + fmaxf(d[mi][nj][3] + bsv[mi][1], 0.f) * wtv[mi][1];
        }
        v0 += __shfl_xor_sync(0xffffffffu, v0, 4);
        v0 += __shfl_xor_sync(0xffffffffu, v0, 8);
        v0 += __shfl_xor_sync(0xffffffffu, v0, 16);
        v1 += __shfl_xor_sync(0xffffffffu, v1, 4);
        v1 += __shfl_xor_sync(0xffffffffu, v1, 8);
        v1 += __shfl_xor_sync(0xffffffffu, v1, 16);
        if (lane < 4) {
            int n = nj * 8 + tid4 * 2;
            atomicAdd(&sCol[n], v0);
            atomicAdd(&sCol[n + 1], v1);
        }
    }
    __syncthreads();

    if (tid < TW) {
        const float btv = bt[0];
        float s = 0.f;
#pragma unroll
        for (int r = 0; r < R; r++)
            s += wpl[h0 + r] * (sCol[r * TW + tid] + btv);
        atomicAdd(&out[b * 240 + BASE + w0 + tid], s);
    }
}

// ---- p5 tile: tidy 1x1 (512->1) + pool over h=8, memory bound -------------
__device__ void p5_tile(int b, const float* __restrict__ p5,
                        const float* __restrict__ wt,
                        const float* __restrict__ bt,
                        const float* __restrict__ wpl,
                        const float* __restrict__ bpl,
                        float* __restrict__ out, char* smem) {
    float* red = (float*)smem;          // 64 floats
    float* spl = (float*)smem + 64;     // 8 floats
    const int tid = threadIdx.x;
    const int w = tid & 15;
    const int g = tid >> 4;
    if (tid < 8) spl[tid] = wpl[tid];
    __syncthreads();

    const float* pb = p5 + (size_t)b * 512 * 8 * 16;
    float accv = 0.f;
    for (int c = g; c < 512; c += 4) {
        float wc = wt[c];
        const float* row = pb + (size_t)c * 8 * 16 + w;
#pragma unroll
        for (int h = 0; h < 8; h++)
            accv = fmaf(wc * spl[h], row[h * 16], accv);
    }
    red[tid] = accv;
    __syncthreads();
    if (tid < 16) {
        float s = 0.f;
#pragma unroll
        for (int gg = 0; gg < 4; gg++) s += red[gg * 16 + tid];
        float sumpl = 0.f;
#pragma unroll
        for (int h = 0; h < 8; h++) sumpl += spl[h];
        out[b * 240 + 224 + tid] = s + bt[0] * sumpl + bpl[0];
    }
}

// ---- fused kernel: all conv levels + p5 in one grid ------------------------
// Tiles (R=2, TW=32): L1 64x(32x4)=8192 | L2 64x(16x2)=2048 | L3 64x(8x1)=512
// blocks: [0,8192) L1 | [8192,10240) L2 | [10240,10752) L3 | [10752,10816) p5
__global__ void __launch_bounds__(64, 5)
fused_kernel(const float* __restrict__ p2, const float* __restrict__ p3,
             const float* __restrict__ p4, const float* __restrict__ p5,
             const uint4* __restrict__ wA,
             const float* __restrict__ bs1, const float* __restrict__ bs2,
             const float* __restrict__ bs3,
             const float* __restrict__ wt1, const float* __restrict__ bt1,
             const float* __restrict__ wt2, const float* __restrict__ bt2,
             const float* __restrict__ wt3, const float* __restrict__ bt3,
             const float* __restrict__ wt4, const float* __restrict__ bt4,
             const float* __restrict__ wpl1, const float* __restrict__ wpl2,
             const float* __restrict__ wpl3, const float* __restrict__ wpl4,
             const float* __restrict__ bpl4,
             float* __restrict__ out) {
    extern __shared__ char smem[];
    const int bid = blockIdx.x;
    if (bid < 8192) {
        conv_tile_impl<64, 128, 0>(bid, p2, wA, bs1, wt1, bt1, wpl1, out, smem);
    } else if (bid < 10240) {
        conv_tile_impl<32, 64, 128>(bid - 8192, p3, wA + 36 * 512,
                                    bs2, wt2, bt2, wpl2, out, smem);
    } else if (bid < 10752) {
        conv_tile_impl<16, 32, 192>(bid - 10240, p4, wA + 72 * 512,
                                    bs3, wt3, bt3, wpl3, out, smem);
    } else {
        p5_tile(bid - 10752, p5, wt4, bt4, wpl4, bpl4, out, smem);
    }
}

// ---------------------------------------------------------------------------
extern "C" void kernel_launch(void* const* d_in, const int* in_sizes, int n_in,
                              void* d_out, int out_size) {
    const float* p2 = (const float*)d_in[0];
    const float* p3 = (const float*)d_in[1];
    const float* p4 = (const float*)d_in[2];
    const float* p5 = (const float*)d_in[3];
    const float* w_s1 = (const float*)d_in[4];
    const float* b_s1 = (const float*)d_in[5];
    const float* w_s2 = (const float*)d_in[6];
    const float* b_s2 = (const float*)d_in[7];
    const float* w_s3 = (const float*)d_in[8];
    const float* b_s3 = (const float*)d_in[9];
    const float* w_t1 = (const float*)d_in[10];
    const float* b_t1 = (const float*)d_in[11];
    const float* w_t2 = (const float*)d_in[12];
    const float* b_t2 = (const float*)d_in[13];
    const float* w_t3 = (const float*)d_in[14];
    const float* b_t3 = (const float*)d_in[15];
    const float* w_t4 = (const float*)d_in[16];
    const float* b_t4 = (const float*)d_in[17];
    const float* w_pl1 = (const float*)d_in[18];
    const float* b_pl1 = (const float*)d_in[19];
    const float* w_pl2 = (const float*)d_in[20];
    const float* b_pl2 = (const float*)d_in[21];
    const float* w_pl3 = (const float*)d_in[22];
    const float* b_pl3 = (const float*)d_in[23];
    const float* w_pl4 = (const float*)d_in[24];
    const float* b_pl4 = (const float*)d_in[25];
    float* out = (float*)d_out;

    prep_kernel<<<(3 * 36 * 2048 + 64 * 224 + 255) / 256, 256>>>(
        w_s1, w_s2, w_s3, b_pl1, b_pl2, b_pl3, out);

    uint4* wAd;
    cudaGetSymbolAddress((void**)&wAd, g_wA);

    cudaFuncSetAttribute(fused_kernel,
                         cudaFuncAttributeMaxDynamicSharedMemorySize,
                         SMEM_BYTES);
    fused_kernel<<<10816, 64, SMEM_BYTES>>>(
        p2, p3, p4, p5, wAd,
        b_s1, b_s2, b_s3,
        w_t1, b_t1, w_t2, b_t2, w_t3, b_t3, w_t4, b_t4,
        w_pl1, w_pl2, w_pl3, w_pl4, b_pl4, out);
}

// round 16
// speedup vs baseline: 2.5577x; 2.5577x over previous
#include <cuda_runtime.h>
#include <cuda_fp16.h>
#include <cstdint>

// ---------------------------------------------------------------------------
// FPN head via legacy tensor cores (mma.sync m16n8k16 f16, fp32 accum).
// R16: R14 config (single-phase staging, one barrier, sync-free MMA stream,
// 64-thr blocks, warp tile 64o x 32n) with __launch_bounds__(64,7):
// reg cap 128 -> 146 so ptxas can software-pipeline the A-fragment LDGs
// across tap iterations (R14 was exactly at the 128-reg cap -> no prefetch).
// R15 lesson: 128-acc tiles spill catastrophically; 64 accs is the ceiling.
// Output: [64, 240] fp32  (c1:128 | c2:64 | c3:32 | c4:16)
// ---------------------------------------------------------------------------

typedef unsigned int u32;

// A fragment image: [l][gi(36)][rg(8)][ks(2)][lane(32)] x uint4
__device__ uint4 g_wA[3 * 36 * 8 * 2 * 32];

// per-block smem: sCol(32f)/p5 scratch @0, B @1024: 72 pos x 256 B
#define SMEM_BYTES 19456   // 1024 + 72*256

// ---- PTX helpers ----------------------------------------------------------
__device__ __forceinline__ u32 smem_u32(const void* p) {
    u32 a;
    asm("{ .reg .u64 t; cvta.to.shared.u64 t, %1; cvt.u32.u64 %0, t; }"
        : "=r"(a) : "l"(p));
    return a;
}
__device__ __forceinline__ void ldm_x4(u32* r, u32 addr) {
    asm volatile("ldmatrix.sync.aligned.m8n8.x4.shared.b16 {%0,%1,%2,%3}, [%4];"
                 : "=r"(r[0]), "=r"(r[1]), "=r"(r[2]), "=r"(r[3]) : "r"(addr));
}
__device__ __forceinline__ void mma16816(float* d, const uint4 a, u32 b0, u32 b1) {
    asm volatile(
        "mma.sync.aligned.m16n8k16.row.col.f32.f16.f16.f32 "
        "{%0,%1,%2,%3}, {%4,%5,%6,%7}, {%8,%9}, {%0,%1,%2,%3};"
        : "+f"(d[0]), "+f"(d[1]), "+f"(d[2]), "+f"(d[3])
        : "r"(a.x), "r"(a.y), "r"(a.z), "r"(a.w), "r"(b0), "r"(b1));
}

// ---- weight prep + out init fused -----------------------------------------
__global__ void prep_kernel(const float* __restrict__ w1,
                            const float* __restrict__ w2,
                            const float* __restrict__ w3,
                            const float* __restrict__ bpl1,
                            const float* __restrict__ bpl2,
                            const float* __restrict__ bpl3,
                            float* __restrict__ out) {
    int i = blockIdx.x * 256 + threadIdx.x;
    if (i < 3 * 36 * 2048) {
        int q    = i & 3;
        int lane = (i >> 2) & 31;
        int ks   = (i >> 7) & 1;
        int rg   = (i >> 8) & 7;
        int gi   = (i >> 11) % 36;
        int l    = i / (36 << 11);
        const float* src = (l == 0) ? w1 : (l == 1) ? w2 : w3;
        int o = rg * 16 + (lane >> 2) + (q & 1) * 8;
        int k = ks * 16 + (lane & 3) * 2 + (q >> 1) * 8;
        int c = (gi / 9) * 32 + k;
        int tap = gi % 9;
        __half2 hv = __floats2half2_rn(src[o * 1152 + c * 9 + tap],
                                       src[o * 1152 + (c + 1) * 9 + tap]);
        ((u32*)g_wA)[i] = *(u32*)&hv;
    } else {
        int j2 = i - 3 * 36 * 2048;
        if (j2 >= 64 * 224) return;
        int j = j2 % 224;
        out[(j2 / 224) * 240 + j] =
            (j < 128) ? bpl1[0] : (j < 192) ? bpl2[0] : bpl3[0];
    }
}

// ---- conv tile worker ------------------------------------------------------
// 64 threads = 2 warps (warpm 0/1, each 64o x 32n). Block tile 128o x 32n =
// R(2) rows x TW(16) cols stripe.
// SMEM: sCol(32f)@0, B @1024: [(R+2)*(TW+2)=72 pos][128 f16 = 256 B],
//   16B-block swizzle: block kb at position p stored at slot kb ^ (p & 7).
template <int H, int W, int BASE>
__device__ void conv_tile_impl(
    int tbid, const float* __restrict__ x, const uint4* __restrict__ wA,
    const float* __restrict__ bs, const float* __restrict__ wt,
    const float* __restrict__ bt, const float* __restrict__ wpl,
    float* __restrict__ out, char* smem) {
    constexpr int TW = 16;
    constexpr int R = 2;
    constexpr int NW = TW + 2;
    constexpr int B_OFF = 1024;
    constexpr int CT = W / TW;
    constexpr int TW4 = TW / 4;

    float* sCol = (float*)smem;
    const u32 smu = smem_u32(smem);
    const u32 bbase = smu + B_OFF;

    const int tid = threadIdx.x;
    const int warpm = tid >> 5;        // 0..1
    const int lane = tid & 31;

    const int TPB = (H / R) * CT;
    const int b = tbid / TPB;
    const int rem = tbid - b * TPB;
    const int h0 = (rem / CT) * R;
    const int w0 = (rem - (rem / CT) * CT) * TW;
    const float* xb = x + (size_t)b * 128 * H * W;

    if (tid < R * TW) sCol[tid] = 0.f;

    // hoisted B-tile geometry (2 ldmatrix groups, each 16 n)
    int p0[2];
#pragma unroll
    for (int j = 0; j < 2; j++) {
        int ng = j * 16 + (lane >> 4) * 8;   // 0,8,16,24
        int trow = ng >> 4;                  // row within R
        int tcol = ng & (TW - 1);
        p0[j] = trow * NW + tcol + (lane & 7);
    }
    const int kbh = (lane >> 3) & 1;

    float d[4][4][4];
#pragma unroll
    for (int mi = 0; mi < 4; mi++)
#pragma unroll
        for (int nj = 0; nj < 4; nj++)
#pragma unroll
            for (int q = 0; q < 4; q++) d[mi][nj][q] = 0.f;

    // ---- single-phase staging: all 128 channels ---------------------------
    {
#pragma unroll 1
        for (int cpr = 0; cpr < 4; cpr++) {
            const int cp = (tid >> 2) + cpr * 16;     // half2 pair 0..63
            const int kb = cp >> 2;                   // 16B block 0..15
            const int cw = cp & 3;                    // u32 within block
            const float* xc0 = xb + (size_t)(2 * cp) * H * W;
            // halo columns (w = -1 and w = TW)
            for (int it = tid & 3; it < (R + 2) * 2; it += 4) {
                int r = it >> 1;
                int w = (it & 1) * (NW - 1);
                int gh = h0 + r - 1;
                int gw = w0 + w - 1;
                float v0 = 0.f, v1 = 0.f;
                if (gh >= 0 && gh < H && (unsigned)gw < (unsigned)W) {
                    const float* bp = xc0 + gh * W + gw;
                    v0 = bp[0];
                    v1 = bp[H * W];
                }
                int p = r * NW + w;
                __half2 hv = __floats2half2_rn(v0, v1);
                int word = p * 64 + ((kb ^ (p & 7)) << 2) + cw;
                *(__half2*)(smem + B_OFF + word * 4) = hv;
            }
            // interior: float4 loads (4 positions per LDG)
            for (int it = tid & 3; it < (R + 2) * TW4; it += 4) {
                int r = it / TW4;
                int w4 = (it - r * TW4) * 4;
                int gh = h0 + r - 1;
                float4 v0 = {0.f, 0.f, 0.f, 0.f}, v1 = v0;
                if (gh >= 0 && gh < H) {
                    const float* bp = xc0 + gh * W + (w0 + w4);
                    v0 = *(const float4*)bp;
                    v1 = *(const float4*)(bp + H * W);
                }
                const float* f0 = (const float*)&v0;
                const float* f1 = (const float*)&v1;
#pragma unroll
                for (int dw = 0; dw < 4; dw++) {
                    int p = r * NW + w4 + dw + 1;
                    __half2 hv = __floats2half2_rn(f0[dw], f1[dw]);
                    int word = p * 64 + ((kb ^ (p & 7)) << 2) + cw;
                    *(__half2*)(smem + B_OFF + word * 4) = hv;
                }
            }
        }
    }
    __syncthreads();   // the ONLY pre-MMA barrier

    // ---- sync-free MMA stream: 4 cc (rolled) x 9 taps x 2 ks --------------
#pragma unroll 1
    for (int cc = 0; cc < 4; cc++) {
#pragma unroll
        for (int tap = 0; tap < 9; tap++) {
            const int gi = cc * 9 + tap;
            const int dy = tap / 3;
            const int dx = tap - dy * 3;
            const int pofs = dy * NW + dx;
#pragma unroll
            for (int ks = 0; ks < 2; ks++) {
                uint4 a[4];
#pragma unroll
                for (int mi = 0; mi < 4; mi++) {
                    int rg = warpm * 4 + mi;
                    a[mi] = wA[((gi * 8 + rg) * 2 + ks) * 32 + lane];
                }
                const int kb = cc * 4 + ks * 2 + kbh;   // 0..15
#pragma unroll
                for (int j = 0; j < 2; j++) {
                    int p = p0[j] + pofs;
                    u32 bf[4];
                    ldm_x4(bf, bbase + p * 256 + ((kb ^ (p & 7)) << 4));
#pragma unroll
                    for (int mi = 0; mi < 4; mi++) {
                        mma16816(d[mi][2 * j], a[mi], bf[0], bf[1]);
                        mma16816(d[mi][2 * j + 1], a[mi], bf[2], bf[3]);
                    }
                }
            }
        }
    }

    // ---- epilogue: bias + ReLU + dot(w_t), reduce, pool -------------------
    const int g = lane >> 2;
    const int tid4 = lane & 3;
    float bsv[4][2], wtv[4][2];
#pragma unroll
    for (int mi = 0; mi < 4; mi++)
#pragma unroll
        for (int hh = 0; hh < 2; hh++) {
            int o = warpm * 64 + mi * 16 + hh * 8 + g;
            bsv[mi][hh] = bs[o];
            wtv[mi][hh] = wt[o];
        }
    __syncthreads();
#pragma unroll
    for (int nj = 0; nj < 4; nj++) {
        float v0 = 0.f, v1 = 0.f;
#pragma unroll
        for (int mi = 0; mi < 4; mi++) {
            v0 += fmaxf(d[mi][nj][0] + bsv[mi][0], 0.f) * wtv[mi][0]
                + fmaxf(d[mi][nj][2] + bsv[mi][1], 0.f) * wtv[mi][1];
            v1 += fmaxf(d[mi][nj][1] + bsv[mi][0], 0.f) * wtv[mi][0]
                + fmaxf(d[mi][nj][3] + bsv[mi][1], 0.f) * wtv[mi][1];
        }
        v0 += __shfl_xor_sync(0xffffffffu, v0, 4);
        v0 += __shfl_xor_sync(0xffffffffu, v0, 8);
        v0 += __shfl_xor_sync(0xffffffffu, v0, 16);
        v1 += __shfl_xor_sync(0xffffffffu, v1, 4);
        v1 += __shfl_xor_sync(0xffffffffu, v1, 8);
        v1 += __shfl_xor_sync(0xffffffffu, v1, 16);
        if (lane < 4) {
            int n = nj * 8 + tid4 * 2;
            atomicAdd(&sCol[n], v0);
            atomicAdd(&sCol[n + 1], v1);
        }
    }
    __syncthreads();

    if (tid < TW) {
        const float btv = bt[0];
        float s = 0.f;
#pragma unroll
        for (int r = 0; r < R; r++)
            s += wpl[h0 + r] * (sCol[r * TW + tid] + btv);
        atomicAdd(&out[b * 240 + BASE + w0 + tid], s);
    }
}

// ---- p5 tile: tidy 1x1 (512->1) + pool over h=8, memory bound -------------
__device__ void p5_tile(int b, const float* __restrict__ p5,
                        const float* __restrict__ wt,
                        const float* __restrict__ bt,
                        const float* __restrict__ wpl,
                        const float* __restrict__ bpl,
                        float* __restrict__ out, char* smem) {
    float* red = (float*)smem;          // 64 floats
    float* spl = (float*)smem + 64;     // 8 floats
    const int tid = threadIdx.x;
    const int w = tid & 15;
    const int g = tid >> 4;
    if (tid < 8) spl[tid] = wpl[tid];
    __syncthreads();

    const float* pb = p5 + (size_t)b * 512 * 8 * 16;
    float accv = 0.f;
    for (int c = g; c < 512; c += 4) {
        float wc = wt[c];
        const float* row = pb + (size_t)c * 8 * 16 + w;
#pragma unroll
        for (int h = 0; h < 8; h++)
            accv = fmaf(wc * spl[h], row[h * 16], accv);
    }
    red[tid] = accv;
    __syncthreads();
    if (tid < 16) {
        float s = 0.f;
#pragma unroll
        for (int gg = 0; gg < 4; gg++) s += red[gg * 16 + tid];
        float sumpl = 0.f;
#pragma unroll
        for (int h = 0; h < 8; h++) sumpl += spl[h];
        out[b * 240 + 224 + tid] = s + bt[0] * sumpl + bpl[0];
    }
}

// ---- fused kernel: all conv levels + p5 in one grid ------------------------
// Tiles (R=2, TW=16): L1 64x(32x8)=16384 | L2 64x(16x4)=4096 | L3 64x(8x2)=1024
// blocks: [0,16384) L1 | [16384,20480) L2 | [20480,21504) L3 | [21504,21568) p5
__global__ void __launch_bounds__(64, 7)
fused_kernel(const float* __restrict__ p2, const float* __restrict__ p3,
             const float* __restrict__ p4, const float* __restrict__ p5,
             const uint4* __restrict__ wA,
             const float* __restrict__ bs1, const float* __restrict__ bs2,
             const float* __restrict__ bs3,
             const float* __restrict__ wt1, const float* __restrict__ bt1,
             const float* __restrict__ wt2, const float* __restrict__ bt2,
             const float* __restrict__ wt3, const float* __restrict__ bt3,
             const float* __restrict__ wt4, const float* __restrict__ bt4,
             const float* __restrict__ wpl1, const float* __restrict__ wpl2,
             const float* __restrict__ wpl3, const float* __restrict__ wpl4,
             const float* __restrict__ bpl4,
             float* __restrict__ out) {
    extern __shared__ char smem[];
    const int bid = blockIdx.x;
    if (bid < 16384) {
        conv_tile_impl<64, 128, 0>(bid, p2, wA, bs1, wt1, bt1, wpl1, out, smem);
    } else if (bid < 20480) {
        conv_tile_impl<32, 64, 128>(bid - 16384, p3, wA + 36 * 512,
                                    bs2, wt2, bt2, wpl2, out, smem);
    } else if (bid < 21504) {
        conv_tile_impl<16, 32, 192>(bid - 20480, p4, wA + 72 * 512,
                                    bs3, wt3, bt3, wpl3, out, smem);
    } else {
        p5_tile(bid - 21504, p5, wt4, bt4, wpl4, bpl4, out, smem);
    }
}

// ---------------------------------------------------------------------------
extern "C" void kernel_launch(void* const* d_in, const int* in_sizes, int n_in,
                              void* d_out, int out_size) {
    const float* p2 = (const float*)d_in[0];
    const float* p3 = (const float*)d_in[1];
    const float* p4 = (const float*)d_in[2];
    const float* p5 = (const float*)d_in[3];
    const float* w_s1 = (const float*)d_in[4];
    const float* b_s1 = (const float*)d_in[5];
    const float* w_s2 = (const float*)d_in[6];
    const float* b_s2 = (const float*)d_in[7];
    const float* w_s3 = (const float*)d_in[8];
    const float* b_s3 = (const float*)d_in[9];
    const float* w_t1 = (const float*)d_in[10];
    const float* b_t1 = (const float*)d_in[11];
    const float* w_t2 = (const float*)d_in[12];
    const float* b_t2 = (const float*)d_in[13];
    const float* w_t3 = (const float*)d_in[14];
    const float* b_t3 = (const float*)d_in[15];
    const float* w_t4 = (const float*)d_in[16];
    const float* b_t4 = (const float*)d_in[17];
    const float* w_pl1 = (const float*)d_in[18];
    const float* b_pl1 = (const float*)d_in[19];
    const float* w_pl2 = (const float*)d_in[20];
    const float* b_pl2 = (const float*)d_in[21];
    const float* w_pl3 = (const float*)d_in[22];
    const float* b_pl3 = (const float*)d_in[23];
    const float* w_pl4 = (const float*)d_in[24];
    const float* b_pl4 = (const float*)d_in[25];
    float* out = (float*)d_out;

    prep_kernel<<<(3 * 36 * 2048 + 64 * 224 + 255) / 256, 256>>>(
        w_s1, w_s2, w_s3, b_pl1, b_pl2, b_pl3, out);

    uint4* wAd;
    cudaGetSymbolAddress((void**)&wAd, g_wA);

    cudaFuncSetAttribute(fused_kernel,
                         cudaFuncAttributeMaxDynamicSharedMemorySize,
                         SMEM_BYTES);
    fused_kernel<<<21568, 64, SMEM_BYTES>>>(
        p2, p3, p4, p5, wAd,
        b_s1, b_s2, b_s3,
        w_t1, b_t1, w_t2, b_t2, w_t3, b_t3, w_t4, b_t4,
        w_pl1, w_pl2, w_pl3, w_pl4, b_pl4, out);
}

// round 17
// speedup vs baseline: 3.0875x; 1.2071x over previous
#include <cuda_runtime.h>
#include <cuda_fp16.h>
#include <cstdint>

// ---------------------------------------------------------------------------
// FPN head via legacy tensor cores (mma.sync m16n8k16 f16, fp32 accum).
// R17: manual software pipeline of the A-fragment LDGs. Flat gi-loop (36
// steps x ks 0/1) with explicit double-buffered A regs (a0/a1): iteration
// i's MMAs overlap iteration i+1's gmem loads. Tap geometry via smem lookup
// tables (no div/mod in loop). launch_bounds(64,7): reg cap 146, 14 warps/SM.
// Rest identical to R14/16: single-phase staging, one barrier, fused launch.
// Output: [64, 240] fp32  (c1:128 | c2:64 | c3:32 | c4:16)
// ---------------------------------------------------------------------------

typedef unsigned int u32;

// A fragment image: [l][gi(36)][rg(8)][ks(2)][lane(32)] x uint4
__device__ uint4 g_wA[3 * 36 * 8 * 2 * 32];

// per-block smem: sCol(32f)@0, tables @512 (pofsT 36 ints, kbcT 36 ints),
// B @1024: 72 pos x 256 B
#define SMEM_BYTES 19456   // 1024 + 72*256

// ---- PTX helpers ----------------------------------------------------------
__device__ __forceinline__ u32 smem_u32(const void* p) {
    u32 a;
    asm("{ .reg .u64 t; cvta.to.shared.u64 t, %1; cvt.u32.u64 %0, t; }"
        : "=r"(a) : "l"(p));
    return a;
}
__device__ __forceinline__ void ldm_x4(u32* r, u32 addr) {
    asm volatile("ldmatrix.sync.aligned.m8n8.x4.shared.b16 {%0,%1,%2,%3}, [%4];"
                 : "=r"(r[0]), "=r"(r[1]), "=r"(r[2]), "=r"(r[3]) : "r"(addr));
}
__device__ __forceinline__ void mma16816(float* d, const uint4 a, u32 b0, u32 b1) {
    asm volatile(
        "mma.sync.aligned.m16n8k16.row.col.f32.f16.f16.f32 "
        "{%0,%1,%2,%3}, {%4,%5,%6,%7}, {%8,%9}, {%0,%1,%2,%3};"
        : "+f"(d[0]), "+f"(d[1]), "+f"(d[2]), "+f"(d[3])
        : "r"(a.x), "r"(a.y), "r"(a.z), "r"(a.w), "r"(b0), "r"(b1));
}

// ---- weight prep + out init fused -----------------------------------------
__global__ void prep_kernel(const float* __restrict__ w1,
                            const float* __restrict__ w2,
                            const float* __restrict__ w3,
                            const float* __restrict__ bpl1,
                            const float* __restrict__ bpl2,
                            const float* __restrict__ bpl3,
                            float* __restrict__ out) {
    int i = blockIdx.x * 256 + threadIdx.x;
    if (i < 3 * 36 * 2048) {
        int q    = i & 3;
        int lane = (i >> 2) & 31;
        int ks   = (i >> 7) & 1;
        int rg   = (i >> 8) & 7;
        int gi   = (i >> 11) % 36;
        int l    = i / (36 << 11);
        const float* src = (l == 0) ? w1 : (l == 1) ? w2 : w3;
        int o = rg * 16 + (lane >> 2) + (q & 1) * 8;
        int k = ks * 16 + (lane & 3) * 2 + (q >> 1) * 8;
        int c = (gi / 9) * 32 + k;
        int tap = gi % 9;
        __half2 hv = __floats2half2_rn(src[o * 1152 + c * 9 + tap],
                                       src[o * 1152 + (c + 1) * 9 + tap]);
        ((u32*)g_wA)[i] = *(u32*)&hv;
    } else {
        int j2 = i - 3 * 36 * 2048;
        if (j2 >= 64 * 224) return;
        int j = j2 % 224;
        out[(j2 / 224) * 240 + j] =
            (j < 128) ? bpl1[0] : (j < 192) ? bpl2[0] : bpl3[0];
    }
}

// ---- conv tile worker ------------------------------------------------------
// 64 threads = 2 warps (warpm 0/1, each 64o x 32n). Block tile 128o x 32n =
// R(2) rows x TW(16) cols stripe.
// SMEM: sCol(32f)@0, pofsT@512, kbcT@656, B @1024: [72 pos][256 B],
//   16B-block swizzle: block kb at position p stored at slot kb ^ (p & 7).
template <int H, int W, int BASE>
__device__ void conv_tile_impl(
    int tbid, const float* __restrict__ x, const uint4* __restrict__ wA,
    const float* __restrict__ bs, const float* __restrict__ wt,
    const float* __restrict__ bt, const float* __restrict__ wpl,
    float* __restrict__ out, char* smem) {
    constexpr int TW = 16;
    constexpr int R = 2;
    constexpr int NW = TW + 2;
    constexpr int B_OFF = 1024;
    constexpr int CT = W / TW;
    constexpr int TW4 = TW / 4;

    float* sCol = (float*)smem;
    int* pofsT = (int*)(smem + 512);     // 36 ints
    int* kbcT  = (int*)(smem + 656);     // 36 ints
    const u32 smu = smem_u32(smem);
    const u32 bbase = smu + B_OFF;

    const int tid = threadIdx.x;
    const int warpm = tid >> 5;        // 0..1
    const int lane = tid & 31;

    const int TPB = (H / R) * CT;
    const int b = tbid / TPB;
    const int rem = tbid - b * TPB;
    const int h0 = (rem / CT) * R;
    const int w0 = (rem - (rem / CT) * CT) * TW;
    const float* xb = x + (size_t)b * 128 * H * W;

    if (tid < R * TW) sCol[tid] = 0.f;
    if (tid < 36) {
        int tap = tid % 9;
        pofsT[tid] = (tap / 3) * NW + (tap % 3);
        kbcT[tid] = (tid / 9) * 4;
    }

    // hoisted B-tile geometry (2 ldmatrix groups, each 16 n)
    int p0[2];
#pragma unroll
    for (int j = 0; j < 2; j++) {
        int ng = j * 16 + (lane >> 4) * 8;   // 0,8,16,24
        int trow = ng >> 4;                  // row within R
        int tcol = ng & (TW - 1);
        p0[j] = trow * NW + tcol + (lane & 7);
    }
    const int kbh = (lane >> 3) & 1;

    float d[4][4][4];
#pragma unroll
    for (int mi = 0; mi < 4; mi++)
#pragma unroll
        for (int nj = 0; nj < 4; nj++)
#pragma unroll
            for (int q = 0; q < 4; q++) d[mi][nj][q] = 0.f;

    // ---- single-phase staging: all 128 channels ---------------------------
    {
#pragma unroll 1
        for (int cpr = 0; cpr < 4; cpr++) {
            const int cp = (tid >> 2) + cpr * 16;     // half2 pair 0..63
            const int kb = cp >> 2;                   // 16B block 0..15
            const int cw = cp & 3;                    // u32 within block
            const float* xc0 = xb + (size_t)(2 * cp) * H * W;
            // halo columns (w = -1 and w = TW)
            for (int it = tid & 3; it < (R + 2) * 2; it += 4) {
                int r = it >> 1;
                int w = (it & 1) * (NW - 1);
                int gh = h0 + r - 1;
                int gw = w0 + w - 1;
                float v0 = 0.f, v1 = 0.f;
                if (gh >= 0 && gh < H && (unsigned)gw < (unsigned)W) {
                    const float* bp = xc0 + gh * W + gw;
                    v0 = bp[0];
                    v1 = bp[H * W];
                }
                int p = r * NW + w;
                __half2 hv = __floats2half2_rn(v0, v1);
                int word = p * 64 + ((kb ^ (p & 7)) << 2) + cw;
                *(__half2*)(smem + B_OFF + word * 4) = hv;
            }
            // interior: float4 loads (4 positions per LDG)
            for (int it = tid & 3; it < (R + 2) * TW4; it += 4) {
                int r = it / TW4;
                int w4 = (it - r * TW4) * 4;
                int gh = h0 + r - 1;
                float4 v0 = {0.f, 0.f, 0.f, 0.f}, v1 = v0;
                if (gh >= 0 && gh < H) {
                    const float* bp = xc0 + gh * W + (w0 + w4);
                    v0 = *(const float4*)bp;
                    v1 = *(const float4*)(bp + H * W);
                }
                const float* f0 = (const float*)&v0;
                const float* f1 = (const float*)&v1;
#pragma unroll
                for (int dw = 0; dw < 4; dw++) {
                    int p = r * NW + w4 + dw + 1;
                    __half2 hv = __floats2half2_rn(f0[dw], f1[dw]);
                    int word = p * 64 + ((kb ^ (p & 7)) << 2) + cw;
                    *(__half2*)(smem + B_OFF + word * 4) = hv;
                }
            }
        }
    }
    __syncthreads();   // the ONLY pre-MMA barrier

    // ---- software-pipelined MMA stream: 36 gi x (ks=0, ks=1) --------------
    // A fragments double-buffered: while gi's MMAs run, gi(+ks) next loads fly.
    const uint4* wAw = wA + (size_t)warpm * 4 * 2 * 32;  // this warp's rg base

#define LOADA(buf, giv, ksv)                                                 \
    do {                                                                     \
        const uint4* ap = wAw + (((giv) * 8) * 2 + (ksv)) * 32 + lane;       \
        (buf)[0] = ap[0];                                                    \
        (buf)[1] = ap[64];                                                   \
        (buf)[2] = ap[128];                                                  \
        (buf)[3] = ap[192];                                                  \
    } while (0)

#define DO_MMAS(buf, pofsv, kbv)                                             \
    do {                                                                     \
        _Pragma("unroll")                                                    \
        for (int j = 0; j < 2; j++) {                                        \
            int p = p0[j] + (pofsv);                                         \
            u32 bf[4];                                                       \
            ldm_x4(bf, bbase + p * 256 + (((kbv) ^ (p & 7)) << 4));          \
            _Pragma("unroll")                                                \
            for (int mi = 0; mi < 4; mi++) {                                 \
                mma16816(d[mi][2 * j], (buf)[mi], bf[0], bf[1]);             \
                mma16816(d[mi][2 * j + 1], (buf)[mi], bf[2], bf[3]);         \
            }                                                                \
        }                                                                    \
    } while (0)

    {
        uint4 a0[4], a1[4];
        LOADA(a0, 0, 0);
#pragma unroll 1
        for (int gi = 0; gi < 36; gi++) {
            const int pofs = pofsT[gi];
            const int kbc = kbcT[gi];
            // prefetch ks=1 of this gi
            LOADA(a1, gi, 1);
            DO_MMAS(a0, pofs, kbc + kbh);
            // prefetch ks=0 of next gi (clamped on last iteration)
            const int gin = (gi < 35) ? gi + 1 : 35;
            LOADA(a0, gin, 0);
            DO_MMAS(a1, pofs, kbc + 2 + kbh);
        }
    }
#undef LOADA
#undef DO_MMAS

    // ---- epilogue: bias + ReLU + dot(w_t), reduce, pool -------------------
    const int g = lane >> 2;
    const int tid4 = lane & 3;
    float bsv[4][2], wtv[4][2];
#pragma unroll
    for (int mi = 0; mi < 4; mi++)
#pragma unroll
        for (int hh = 0; hh < 2; hh++) {
            int o = warpm * 64 + mi * 16 + hh * 8 + g;
            bsv[mi][hh] = bs[o];
            wtv[mi][hh] = wt[o];
        }
    __syncthreads();
#pragma unroll
    for (int nj = 0; nj < 4; nj++) {
        float v0 = 0.f, v1 = 0.f;
#pragma unroll
        for (int mi = 0; mi < 4; mi++) {
            v0 += fmaxf(d[mi][nj][0] + bsv[mi][0], 0.f) * wtv[mi][0]
                + fmaxf(d[mi][nj][2] + bsv[mi][1], 0.f) * wtv[mi][1];
            v1 += fmaxf(d[mi][nj][1] + bsv[mi][0], 0.f) * wtv[mi][0]
                + fmaxf(d[mi][nj][3] + bsv[mi][1], 0.f) * wtv[mi][1];
        }
        v0 += __shfl_xor_sync(0xffffffffu, v0, 4);
        v0 += __shfl_xor_sync(0xffffffffu, v0, 8);
        v0 += __shfl_xor_sync(0xffffffffu, v0, 16);
        v1 += __shfl_xor_sync(0xffffffffu, v1, 4);
        v1 += __shfl_xor_sync(0xffffffffu, v1, 8);
        v1 += __shfl_xor_sync(0xffffffffu, v1, 16);
        if (lane < 4) {
            int n = nj * 8 + tid4 * 2;
            atomicAdd(&sCol[n], v0);
            atomicAdd(&sCol[n + 1], v1);
        }
    }
    __syncthreads();

    if (tid < TW) {
        const float btv = bt[0];
        float s = 0.f;
#pragma unroll
        for (int r = 0; r < R; r++)
            s += wpl[h0 + r] * (sCol[r * TW + tid] + btv);
        atomicAdd(&out[b * 240 + BASE + w0 + tid], s);
    }
}

// ---- p5 tile: tidy 1x1 (512->1) + pool over h=8, memory bound -------------
__device__ void p5_tile(int b, const float* __restrict__ p5,
                        const float* __restrict__ wt,
                        const float* __restrict__ bt,
                        const float* __restrict__ wpl,
                        const float* __restrict__ bpl,
                        float* __restrict__ out, char* smem) {
    float* red = (float*)smem;          // 64 floats
    float* spl = (float*)smem + 64;     // 8 floats
    const int tid = threadIdx.x;
    const int w = tid & 15;
    const int g = tid >> 4;
    if (tid < 8) spl[tid] = wpl[tid];
    __syncthreads();

    const float* pb = p5 + (size_t)b * 512 * 8 * 16;
    float accv = 0.f;
    for (int c = g; c < 512; c += 4) {
        float wc = wt[c];
        const float* row = pb + (size_t)c * 8 * 16 + w;
#pragma unroll
        for (int h = 0; h < 8; h++)
            accv = fmaf(wc * spl[h], row[h * 16], accv);
    }
    red[tid] = accv;
    __syncthreads();
    if (tid < 16) {
        float s = 0.f;
#pragma unroll
        for (int gg = 0; gg < 4; gg++) s += red[gg * 16 + tid];
        float sumpl = 0.f;
#pragma unroll
        for (int h = 0; h < 8; h++) sumpl += spl[h];
        out[b * 240 + 224 + tid] = s + bt[0] * sumpl + bpl[0];
    }
}

// ---- fused kernel: all conv levels + p5 in one grid ------------------------
// Tiles (R=2, TW=16): L1 64x(32x8)=16384 | L2 64x(16x4)=4096 | L3 64x(8x2)=1024
// blocks: [0,16384) L1 | [16384,20480) L2 | [20480,21504) L3 | [21504,21568) p5
__global__ void __launch_bounds__(64, 7)
fused_kernel(const float* __restrict__ p2, const float* __restrict__ p3,
             const float* __restrict__ p4, const float* __restrict__ p5,
             const uint4* __restrict__ wA,
             const float* __restrict__ bs1, const float* __restrict__ bs2,
             const float* __restrict__ bs3,
             const float* __restrict__ wt1, const float* __restrict__ bt1,
             const float* __restrict__ wt2, const float* __restrict__ bt2,
             const float* __restrict__ wt3, const float* __restrict__ bt3,
             const float* __restrict__ wt4, const float* __restrict__ bt4,
             const float* __restrict__ wpl1, const float* __restrict__ wpl2,
             const float* __restrict__ wpl3, const float* __restrict__ wpl4,
             const float* __restrict__ bpl4,
             float* __restrict__ out) {
    extern __shared__ char smem[];
    const int bid = blockIdx.x;
    if (bid < 16384) {
        conv_tile_impl<64, 128, 0>(bid, p2, wA, bs1, wt1, bt1, wpl1, out, smem);
    } else if (bid < 20480) {
        conv_tile_impl<32, 64, 128>(bid - 16384, p3, wA + 36 * 512,
                                    bs2, wt2, bt2, wpl2, out, smem);
    } else if (bid < 21504) {
        conv_tile_impl<16, 32, 192>(bid - 20480, p4, wA + 72 * 512,
                                    bs3, wt3, bt3, wpl3, out, smem);
    } else {
        p5_tile(bid - 21504, p5, wt4, bt4, wpl4, bpl4, out, smem);
    }
}

// ---------------------------------------------------------------------------
extern "C" void kernel_launch(void* const* d_in, const int* in_sizes, int n_in,
                              void* d_out, int out_size) {
    const float* p2 = (const float*)d_in[0];
    const float* p3 = (const float*)d_in[1];
    const float* p4 = (const float*)d_in[2];
    const float* p5 = (const float*)d_in[3];
    const float* w_s1 = (const float*)d_in[4];
    const float* b_s1 = (const float*)d_in[5];
    const float* w_s2 = (const float*)d_in[6];
    const float* b_s2 = (const float*)d_in[7];
    const float* w_s3 = (const float*)d_in[8];
    const float* b_s3 = (const float*)d_in[9];
    const float* w_t1 = (const float*)d_in[10];
    const float* b_t1 = (const float*)d_in[11];
    const float* w_t2 = (const float*)d_in[12];
    const float* b_t2 = (const float*)d_in[13];
    const float* w_t3 = (const float*)d_in[14];
    const float* b_t3 = (const float*)d_in[15];
    const float* w_t4 = (const float*)d_in[16];
    const float* b_t4 = (const float*)d_in[17];
    const float* w_pl1 = (const float*)d_in[18];
    const float* b_pl1 = (const float*)d_in[19];
    const float* w_pl2 = (const float*)d_in[20];
    const float* b_pl2 = (const float*)d_in[21];
    const float* w_pl3 = (const float*)d_in[22];
    const float* b_pl3 = (const float*)d_in[23];
    const float* w_pl4 = (const float*)d_in[24];
    const float* b_pl4 = (const float*)d_in[25];
    float* out = (float*)d_out;

    prep_kernel<<<(3 * 36 * 2048 + 64 * 224 + 255) / 256, 256>>>(
        w_s1, w_s2, w_s3, b_pl1, b_pl2, b_pl3, out);

    uint4* wAd;
    cudaGetSymbolAddress((void**)&wAd, g_wA);

    cudaFuncSetAttribute(fused_kernel,
                         cudaFuncAttributeMaxDynamicSharedMemorySize,
                         SMEM_BYTES);
    fused_kernel<<<21568, 64, SMEM_BYTES>>>(
        p2, p3, p4, p5, wAd,
        b_s1, b_s2, b_s3,
        w_t1, b_t1, w_t2, b_t2, w_t3, b_t3, w_t4, b_t4,
        w_pl1, w_pl2, w_pl3, w_pl4, b_pl4, out);
}